// round 2
// baseline (speedup 1.0000x reference)
#include <cuda_runtime.h>
#include <math.h>

// LIF_R step for N=8192 neurons.
// Dominant cost: w @ g, w is 8192x8192 fp32 = 256 MB -> pure HBM stream.
// One warp per row; g staged in shared; pointwise LIF fused on lane 0.

#define N_NEURONS 8192
#define WARPS_PER_BLOCK 8
#define THREADS_PER_BLOCK (WARPS_PER_BLOCK * 32)

// LIF constants (match reference)
#define C_M_INV 20.0f          // 1 / 0.05
#define F_V 0.15f
#define DELTA_V 12.0f

__global__ __launch_bounds__(THREADS_PER_BLOCK)
void lif_r_kernel(const float* __restrict__ x_in,
                  const float* __restrict__ v,
                  const float* __restrict__ g,
                  const float* __restrict__ theta_s,
                  const float* __restrict__ w,
                  const float* __restrict__ v_rest,
                  const float* __restrict__ /*tau_g*/,
                  float* __restrict__ out)
{
    __shared__ float sg[N_NEURONS];  // 32 KB

    // Stage g into shared (vectorized, all 256 threads)
    {
        const float4* g4 = reinterpret_cast<const float4*>(g);
        float4* sg4 = reinterpret_cast<float4*>(sg);
        for (int i = threadIdx.x; i < N_NEURONS / 4; i += THREADS_PER_BLOCK)
            sg4[i] = g4[i];
    }
    __syncthreads();

    const int warp = threadIdx.x >> 5;
    const int lane = threadIdx.x & 31;
    const int row  = blockIdx.x * WARPS_PER_BLOCK + warp;
    if (row >= N_NEURONS) return;

    const float4* __restrict__ wrow =
        reinterpret_cast<const float4*>(w + (size_t)row * N_NEURONS);
    const float4* __restrict__ sg4 = reinterpret_cast<const float4*>(sg);

    // 8192 / 4 = 2048 float4 per row; 64 per lane. Unroll 8 for MLP.
    float acc = 0.0f;
    #pragma unroll 8
    for (int i = lane; i < N_NEURONS / 4; i += 32) {
        float4 wv = wrow[i];
        float4 gv = sg4[i];
        acc = fmaf(wv.x, gv.x, acc);
        acc = fmaf(wv.y, gv.y, acc);
        acc = fmaf(wv.z, gv.z, acc);
        acc = fmaf(wv.w, gv.w, acc);
    }

    // Warp tree reduction
    #pragma unroll
    for (int off = 16; off > 0; off >>= 1)
        acc += __shfl_xor_sync(0xFFFFFFFFu, acc, off);

    if (lane == 0) {
        const float I  = acc + x_in[row];
        const float vv = v[row];
        const float vr = v_rest[row];
        const float th = theta_s[row];

        // dv = v_rest - v + I/C_M; v_next = v + dv
        const float v_next = vv + (vr - vv + I * C_M_INV);

        // soft spike indicator (returned)
        const float soft = 1.0f / (1.0f + expf(-(v_next - th)));

        // hard spike gating for v reset
        const bool spiked = (v_next >= th);
        const float v_reset = vr + F_V * (vv - vr) - DELTA_V;
        const float v_new = spiked ? v_reset : v_next;

        out[row] = v_new;
        out[N_NEURONS + row] = soft;
    }
}

extern "C" void kernel_launch(void* const* d_in, const int* in_sizes, int n_in,
                              void* d_out, int out_size)
{
    // metadata order: x_in, v, g, theta_s, w, v_rest, tau_g
    const float* x_in    = (const float*)d_in[0];
    const float* v       = (const float*)d_in[1];
    const float* g       = (const float*)d_in[2];
    const float* theta_s = (const float*)d_in[3];
    const float* w       = (const float*)d_in[4];
    const float* v_rest  = (const float*)d_in[5];
    const float* tau_g   = (const float*)d_in[6];
    float* out = (float*)d_out;

    const int blocks = N_NEURONS / WARPS_PER_BLOCK;  // 1024
    lif_r_kernel<<<blocks, THREADS_PER_BLOCK>>>(
        x_in, v, g, theta_s, w, v_rest, tau_g, out);
}

// round 3
// speedup vs baseline: 1.0966x; 1.0966x over previous
#include <cuda_runtime.h>
#include <math.h>

// LIF_R step for N=8192 neurons. Dominant cost: w @ g (8192x8192 fp32 = 256 MB,
// streamed once from HBM). Persistent CTAs + warp-level work stealing remove
// the 2-wave tail that capped R2 at DRAM=60%.

#define N_NEURONS 8192
#define NF4 (N_NEURONS / 4)          // 2048 float4 per row
#define WARPS_PER_BLOCK 8
#define THREADS_PER_BLOCK (WARPS_PER_BLOCK * 32)
#define NUM_BLOCKS 912               // ~6 CTAs/SM * 152 SMs on GB300

#define C_M_INV 20.0f                // 1 / 0.05
#define F_V 0.15f
#define DELTA_V 12.0f

__device__ unsigned int g_row_ctr;

__global__ void reset_ctr_kernel() { g_row_ctr = 0u; }

__global__ __launch_bounds__(THREADS_PER_BLOCK)
void lif_r_kernel(const float* __restrict__ x_in,
                  const float* __restrict__ v,
                  const float* __restrict__ g,
                  const float* __restrict__ theta_s,
                  const float* __restrict__ w,
                  const float* __restrict__ v_rest,
                  float* __restrict__ out)
{
    __shared__ float sg[N_NEURONS];  // 32 KB

    // Stage g into shared once per CTA
    {
        const float4* g4 = reinterpret_cast<const float4*>(g);
        float4* s4 = reinterpret_cast<float4*>(sg);
        for (int i = threadIdx.x; i < NF4; i += THREADS_PER_BLOCK)
            s4[i] = g4[i];
    }
    __syncthreads();

    const int lane = threadIdx.x & 31;
    const float4* __restrict__ sg4 = reinterpret_cast<const float4*>(sg);

    for (;;) {
        // Warp-level work stealing: lane 0 grabs the next row.
        unsigned int row;
        if (lane == 0) row = atomicAdd(&g_row_ctr, 1u);
        row = __shfl_sync(0xFFFFFFFFu, row, 0);
        if (row >= N_NEURONS) break;

        const float4* __restrict__ wrow =
            reinterpret_cast<const float4*>(w + (size_t)row * N_NEURONS);

        // 2048 float4 / 32 lanes = 64 per lane; 4 independent accumulator
        // chains, 4 front-batched LDG.128 per step for MLP.
        float a0 = 0.0f, a1 = 0.0f, a2 = 0.0f, a3 = 0.0f;
        #pragma unroll 4
        for (int i = lane; i < NF4; i += 128) {
            float4 w0 = wrow[i];
            float4 w1 = wrow[i + 32];
            float4 w2 = wrow[i + 64];
            float4 w3 = wrow[i + 96];
            float4 g0 = sg4[i];
            float4 g1 = sg4[i + 32];
            float4 g2 = sg4[i + 64];
            float4 g3 = sg4[i + 96];
            a0 = fmaf(w0.x, g0.x, a0); a0 = fmaf(w0.y, g0.y, a0);
            a0 = fmaf(w0.z, g0.z, a0); a0 = fmaf(w0.w, g0.w, a0);
            a1 = fmaf(w1.x, g1.x, a1); a1 = fmaf(w1.y, g1.y, a1);
            a1 = fmaf(w1.z, g1.z, a1); a1 = fmaf(w1.w, g1.w, a1);
            a2 = fmaf(w2.x, g2.x, a2); a2 = fmaf(w2.y, g2.y, a2);
            a2 = fmaf(w2.z, g2.z, a2); a2 = fmaf(w2.w, g2.w, a2);
            a3 = fmaf(w3.x, g3.x, a3); a3 = fmaf(w3.y, g3.y, a3);
            a3 = fmaf(w3.z, g3.z, a3); a3 = fmaf(w3.w, g3.w, a3);
        }
        float acc = (a0 + a1) + (a2 + a3);

        #pragma unroll
        for (int off = 16; off > 0; off >>= 1)
            acc += __shfl_xor_sync(0xFFFFFFFFu, acc, off);

        if (lane == 0) {
            const float I  = acc + x_in[row];
            const float vv = v[row];
            const float vr = v_rest[row];
            const float th = theta_s[row];

            const float v_next = vv + (vr - vv + I * C_M_INV);
            const float soft = 1.0f / (1.0f + expf(-(v_next - th)));
            const bool spiked = (v_next >= th);
            const float v_reset = vr + F_V * (vv - vr) - DELTA_V;
            const float v_new = spiked ? v_reset : v_next;

            out[row] = v_new;
            out[N_NEURONS + row] = soft;
        }
    }
}

extern "C" void kernel_launch(void* const* d_in, const int* in_sizes, int n_in,
                              void* d_out, int out_size)
{
    // metadata order: x_in, v, g, theta_s, w, v_rest, tau_g
    const float* x_in    = (const float*)d_in[0];
    const float* v       = (const float*)d_in[1];
    const float* g       = (const float*)d_in[2];
    const float* theta_s = (const float*)d_in[3];
    const float* w       = (const float*)d_in[4];
    const float* v_rest  = (const float*)d_in[5];
    float* out = (float*)d_out;

    reset_ctr_kernel<<<1, 1>>>();
    lif_r_kernel<<<NUM_BLOCKS, THREADS_PER_BLOCK>>>(
        x_in, v, g, theta_s, w, v_rest, out);
}